// round 1
// baseline (speedup 1.0000x reference)
#include <cuda_runtime.h>
#include <cuda_bf16.h>
#include <cstdint>

// Problem shapes (fixed by the dataset):
//   messages:          (B=32, E=8192, D=128) fp32   -> d_in[0]
//   tgt_indices:       (B=32, E=8192)        int32  -> d_in[1]
//   atom_features_ref: (B=32, N=2048, D=128) fp32   -> d_in[2] (only shape used)
//   out:               (B=32, N=2048, D=128) fp32
static constexpr int B = 32;
static constexpr int E = 8192;
static constexpr int N = 2048;
static constexpr int D = 128;            // 128 floats = 32 float4 = one warp's lanes

// One warp per edge row. Lane l handles float4 #l of the 512-byte row.
// Scatter via vectorized no-return atomic red.global.add.v4.f32 (sm_90+),
// which lands in L2 (32 MiB output is fully L2-resident).
__global__ __launch_bounds__(256) void scatter_add_kernel(
    const float4* __restrict__ messages,   // (B*E, 32) float4
    const int*    __restrict__ tgt,        // (B*E,)
    float*        __restrict__ out)        // (B*N*D,)
{
    const int warp_in_block = threadIdx.x >> 5;
    const int lane          = threadIdx.x & 31;
    const int row           = blockIdx.x * 8 + warp_in_block;   // 8 warps/block
    // grid sized exactly: B*E rows total
    const int b = row >> 13;               // row / E (E = 8192)

    // Broadcast the target index from lane 0 (single LDG instead of 32).
    int t = 0;
    if (lane == 0) t = __ldg(&tgt[row]);
    t = __shfl_sync(0xFFFFFFFFu, t, 0);

    const float4 v = __ldg(&messages[(size_t)row * 32 + lane]);

    float* dst = out + ((size_t)(b * N + t) * D) + lane * 4;
#if __CUDA_ARCH__ >= 900
    asm volatile(
        "red.global.add.v4.f32 [%0], {%1, %2, %3, %4};"
        :: "l"(dst), "f"(v.x), "f"(v.y), "f"(v.z), "f"(v.w)
        : "memory");
#else
    atomicAdd(dst + 0, v.x);
    atomicAdd(dst + 1, v.y);
    atomicAdd(dst + 2, v.z);
    atomicAdd(dst + 3, v.w);
#endif
}

extern "C" void kernel_launch(void* const* d_in, const int* in_sizes, int n_in,
                              void* d_out, int out_size)
{
    const float4* messages = (const float4*)d_in[0];
    const int*    tgt      = (const int*)d_in[1];
    float*        out      = (float*)d_out;

    // Output is poisoned to 0xAA before timing: zero it (graph-capturable memset node).
    cudaMemsetAsync(d_out, 0, (size_t)out_size * sizeof(float), 0);

    const int total_rows = B * E;          // 262144 warps
    const int warps_per_block = 8;         // 256 threads
    const int blocks = total_rows / warps_per_block;
    scatter_add_kernel<<<blocks, 256>>>(messages, tgt, out);
}

// round 2
// speedup vs baseline: 1.1566x; 1.1566x over previous
#include <cuda_runtime.h>
#include <cuda_bf16.h>
#include <cstdint>

// Shapes (fixed by dataset):
//   messages (B=32, E=8192, D=128) fp32 | tgt (B=32, E=8192) int32
//   out      (B=32, N=2048, D=128) fp32
static constexpr int B = 32;
static constexpr int E = 8192;
static constexpr int N = 2048;
static constexpr int D = 128;          // 128 floats = 32 float4 -> one warp row
static constexpr int ROWS = 4;         // edge rows per warp (MLP batching)
static constexpr int WARPS = 8;        // per block

// One warp handles ROWS consecutive edge rows.
//  - indices: lanes 0..ROWS-1 do one coalesced LDG, broadcast via shfl
//  - messages: __ldcs (evict-first) so the 128MiB stream doesn't evict the
//    32MiB output working set from L2 (atomics must stay L2-resident)
//  - scatter: red.global.add.v4.f32 (no-return vector atomic, lands in L2)
__global__ __launch_bounds__(WARPS * 32) void scatter_add_kernel(
    const float4* __restrict__ messages,   // (B*E, 32) float4
    const int*    __restrict__ tgt,        // (B*E,)
    float*        __restrict__ out)        // (B*N*D,)
{
    const int warp = blockIdx.x * WARPS + (threadIdx.x >> 5);
    const int lane = threadIdx.x & 31;
    const int row0 = warp * ROWS;

    // Coalesced index fetch: lane r loads tgt[row0 + r] for r < ROWS.
    int t = 0;
    if (lane < ROWS) t = __ldg(&tgt[row0 + lane]);

    // Front-batch all ROWS row-loads (4 outstanding LDG.128 per thread).
    float4 v[ROWS];
#pragma unroll
    for (int r = 0; r < ROWS; r++)
        v[r] = __ldcs(&messages[(size_t)(row0 + r) * 32 + lane]);

#pragma unroll
    for (int r = 0; r < ROWS; r++) {
        const int tr  = __shfl_sync(0xFFFFFFFFu, t, r);
        const int b   = (row0 + r) >> 13;              // row / E
        float* dst = out + ((size_t)(b * N + tr) * D) + lane * 4;
        asm volatile(
            "red.global.add.v4.f32 [%0], {%1, %2, %3, %4};"
            :: "l"(dst), "f"(v[r].x), "f"(v[r].y), "f"(v[r].z), "f"(v[r].w)
            : "memory");
    }
}

extern "C" void kernel_launch(void* const* d_in, const int* in_sizes, int n_in,
                              void* d_out, int out_size)
{
    const float4* messages = (const float4*)d_in[0];
    const int*    tgt      = (const int*)d_in[1];
    float*        out      = (float*)d_out;

    // Output is poisoned before timing — zero it (graph-capturable memset node).
    cudaMemsetAsync(d_out, 0, (size_t)out_size * sizeof(float), 0);

    const int total_rows = B * E;                          // 262144
    const int rows_per_block = WARPS * ROWS;               // 32
    const int blocks = total_rows / rows_per_block;        // 8192
    scatter_add_kernel<<<blocks, WARPS * 32>>>(messages, tgt, out);
}